// round 8
// baseline (speedup 1.0000x reference)
#include <cuda_runtime.h>
#include <cuda_bf16.h>

// Shapes (fixed): B=2, N=2048, K=48, A=4
// X: (B,N,4,3) f32; edge_idx: (B,N,48) i32; C: (B,N) i32
// out: (B,N,48,192) f32
//
// R = Q*diag(s): Q orthonormal, s_y=||n_y||. Rotate atoms once by Q^T
// (norm-preserving); per pair: diff + rsqrt + per-axis (mask*s_y).
//
// Output in float8 (st.global.v8.f32, sm_100a 256-bit stores):
// thread t stores float8 index f8 = t + 384q, q=0..2 -> coalesced STG.256.
// 384 = 16*24 -> r8 = t%24 and the pair/component split are loop-invariant;
// k = t/24 + 16q. Each float8 needs 3 pairs (4 if c0==2).

#define BB 2
#define NN 2048
#define KK 48
#define EPS 0.1f
#define THREADS 384
#define ROWF 32                  // padded floats per k row (128 B)

__global__ __launch_bounds__(THREADS) void edge_orient_kernel(
    const float* __restrict__ X,
    const int*   __restrict__ E,
    const int*   __restrict__ C,
    float*       __restrict__ out)
{
    const int bn = blockIdx.x;
    const int b  = bn >> 11;          // / NN
    const int t  = threadIdx.x;

    __shared__ __align__(16) float  sA[KK][ROWF];   // Q^T-rotated, padded
    __shared__ __align__(16) float4 sMS[KK];        // mask*scales per k
    __shared__ int   sJ[KK];
    __shared__ float sR[9];
    __shared__ float sS[3];

    const int* e_row = E + (size_t)bn * KK;

    // ---- phase 1: neighbor indices + frame ----
    if (t < KK) sJ[t] = e_row[t];
    if (t == 64) {
        const float* xr = X + (size_t)bn * 12;
        float Nx = xr[0], Ny = xr[1], Nz = xr[2];
        float Ax = xr[3], Ay = xr[4], Az = xr[5];
        float Cx = xr[6], Cy = xr[7], Cz = xr[8];

        float ux = Nx - Ax, uy = Ny - Ay, uz = Nz - Az;
        float invE = rsqrtf(ux*ux + uy*uy + uz*uz + EPS);
        float n1x = ux*invE, n1y = uy*invE, n1z = uz*invE;
        float n1n2 = n1x*n1x + n1y*n1y + n1z*n1z;
        float inv0 = rsqrtf(n1n2);
        float q1x = n1x*inv0, q1y = n1y*inv0, q1z = n1z*inv0;
        float s1  = n1n2 * inv0;

        float vx = Cx - Ax, vy = Cy - Ay, vz = Cz - Az;
        float invV = rsqrtf(vx*vx + vy*vy + vz*vz + EPS);
        vx *= invV; vy *= invV; vz *= invV;

        float c2x = n1y*vz - n1z*vy;
        float c2y = n1z*vx - n1x*vz;
        float c2z = n1x*vy - n1y*vx;
        invE = rsqrtf(c2x*c2x + c2y*c2y + c2z*c2z + EPS);
        float n2x = c2x*invE, n2y = c2y*invE, n2z = c2z*invE;
        float n2n2 = n2x*n2x + n2y*n2y + n2z*n2z;
        inv0 = rsqrtf(n2n2);
        float q2x = n2x*inv0, q2y = n2y*inv0, q2z = n2z*inv0;
        float s2  = n2n2 * inv0;

        float c3x = n1y*n2z - n1z*n2y;
        float c3y = n1z*n2x - n1x*n2z;
        float c3z = n1x*n2y - n1y*n2x;
        invE = rsqrtf(c3x*c3x + c3y*c3y + c3z*c3z + EPS);
        float n3x = c3x*invE, n3y = c3y*invE, n3z = c3z*invE;
        float n3n2 = n3x*n3x + n3y*n3y + n3z*n3z;
        inv0 = rsqrtf(n3n2);

        sR[0] = q1x;      sR[1] = q1y;      sR[2] = q1z;
        sR[3] = q2x;      sR[4] = q2y;      sR[5] = q2z;
        sR[6] = n3x*inv0; sR[7] = n3y*inv0; sR[8] = n3z*inv0;
        sS[0] = s1; sS[1] = s2; sS[2] = n3n2 * inv0;
    }
    __syncthreads();

    // ---- phase 2: rotate atoms from global into padded smem; fold mask*s ----
    {
        const int k = t >> 3;
        const int a = t & 7;
        const int j = sJ[k];
        const float* src = (a < 4)
            ? (X + (size_t)bn * 12 + 3 * a)
            : (X + ((size_t)(b * NN + j)) * 12 + 3 * (a - 4));
        const float x = src[0], y = src[1], z = src[2];
        const float rx = x*sR[0] + y*sR[1] + z*sR[2];
        const float ry = x*sR[3] + y*sR[4] + z*sR[5];
        const float rz = x*sR[6] + y*sR[7] + z*sR[8];
        *(float4*)&sA[k][4 * a] = make_float4(rx, ry, rz, 0.0f);

        if (a == 0) {
            const float mk = ((C[bn] > 0) && (C[b * NN + j] > 0)) ? 1.0f : 0.0f;
            sMS[k] = make_float4(mk * sS[0], mk * sS[1], mk * sS[2], 0.0f);
        }
    }
    __syncthreads();

    // ---- phase 3: float8 outputs, loop-invariant split ----
    const int k0 = t / 24;            // 0..15
    const int r8 = t - k0 * 24;       // float8 index within k row (invariant)
    const int fr = 8 * r8;            // first float (0..184)
    const int s0 = fr / 3;            // first pair
    const int c0 = fr - 3 * s0;       // 0..2

    // pair atom indices (float4 slot within row), invariant
    const int pA0 = (s0     ) >> 3, pB0 = (s0     ) & 7;
    const int pA1 = (s0 + 1 ) >> 3, pB1 = (s0 + 1 ) & 7;
    const int pA2 = (s0 + 2 ) >> 3, pB2 = (s0 + 2 ) & 7;
    const int pA3 = (s0 + 3 ) >> 3, pB3 = (s0 + 3 ) & 7;   // used iff c0==2

    float* obase = out + (size_t)bn * (KK * 192) + 8 * t;

#pragma unroll
    for (int q = 0; q < 3; q++) {
        const int k = k0 + 16 * q;
        const float4* row = (const float4*)&sA[k][0];
        const float4 ms = sMS[k];

        float p0x, p0y, p0z, p1x, p1y, p1z, p2x, p2y, p2z;
        {
            const float4 A = row[pA0], B = row[pB0];
            const float dx = B.x - A.x, dy = B.y - A.y, dz = B.z - A.z;
            const float inv = rsqrtf(dx*dx + dy*dy + dz*dz + EPS);
            p0x = dx*inv*ms.x; p0y = dy*inv*ms.y; p0z = dz*inv*ms.z;
        }
        {
            const float4 A = row[pA1], B = row[pB1];
            const float dx = B.x - A.x, dy = B.y - A.y, dz = B.z - A.z;
            const float inv = rsqrtf(dx*dx + dy*dy + dz*dz + EPS);
            p1x = dx*inv*ms.x; p1y = dy*inv*ms.y; p1z = dz*inv*ms.z;
        }
        {
            const float4 A = row[pA2], B = row[pB2];
            const float dx = B.x - A.x, dy = B.y - A.y, dz = B.z - A.z;
            const float inv = rsqrtf(dx*dx + dy*dy + dz*dz + EPS);
            p2x = dx*inv*ms.x; p2y = dy*inv*ms.y; p2z = dz*inv*ms.z;
        }

        float o0, o1, o2, o3, o4, o5, o6, o7;
        if (c0 == 0) {
            o0 = p0x; o1 = p0y; o2 = p0z; o3 = p1x;
            o4 = p1y; o5 = p1z; o6 = p2x; o7 = p2y;
        } else if (c0 == 1) {
            o0 = p0y; o1 = p0z; o2 = p1x; o3 = p1y;
            o4 = p1z; o5 = p2x; o6 = p2y; o7 = p2z;
        } else {
            const float4 A = row[pA3], B = row[pB3];
            const float dx = B.x - A.x, dy = B.y - A.y, dz = B.z - A.z;
            const float inv = rsqrtf(dx*dx + dy*dy + dz*dz + EPS);
            const float p3x = dx*inv*ms.x;
            o0 = p0z; o1 = p1x; o2 = p1y; o3 = p1z;
            o4 = p2x; o5 = p2y; o6 = p2z; o7 = p3x;
        }

        // 256-bit coalesced store (sm_100a)
        asm volatile(
            "st.global.v8.f32 [%0], {%1, %2, %3, %4, %5, %6, %7, %8};"
            :: "l"(obase + (size_t)THREADS * 8 * q),
               "f"(o0), "f"(o1), "f"(o2), "f"(o3),
               "f"(o4), "f"(o5), "f"(o6), "f"(o7)
            : "memory");
    }
}

extern "C" void kernel_launch(void* const* d_in, const int* in_sizes, int n_in,
                              void* d_out, int out_size) {
    const float* X = (const float*)d_in[0];
    const int*   E = (const int*)d_in[1];
    const int*   C = (const int*)d_in[2];
    float* out = (float*)d_out;

    edge_orient_kernel<<<BB * NN, THREADS>>>(X, E, C, out);
}